// round 15
// baseline (speedup 1.0000x reference)
#include <cuda_runtime.h>
#include <cuda_bf16.h>
#include <cuda_fp16.h>
#include <cstdint>

#define BB 2048
#define SS 256
#define DD 768
#define CC 100
#define NP 128         // padded N for gemm2
#define PSL 2          // pooling sequence slices (128 tokens each)
#define G2K 4          // gemm2 K slices (192 each)

// Scratch (no cudaMalloc allowed)
__device__ __half g_emb16[(size_t)30522 * DD];
__device__ float g_part[PSL][BB][DD];
__device__ float g_cntf[PSL][BB];
__device__ float g_p2[G2K][BB][NP];
__device__ __nv_bfloat16 g_bow_hi[(size_t)BB * DD];
__device__ __nv_bfloat16 g_bow_lo[(size_t)BB * DD];
__device__ __nv_bfloat16 g_w1_hi[(size_t)DD * DD];    // W1 row-major [K][N]
__device__ __nv_bfloat16 g_w1_lo[(size_t)DD * DD];
__device__ __nv_bfloat16 g_w2p_hi[(size_t)DD * NP];   // W2 padded [K][128]
__device__ __nv_bfloat16 g_w2p_lo[(size_t)DD * NP];
__device__ __nv_bfloat16 g_h_hi[(size_t)BB * DD];
__device__ __nv_bfloat16 g_h_lo[(size_t)BB * DD];

// ---------------------------------------------------------------------------
// Convert embedding table fp32 -> fp16.
// ---------------------------------------------------------------------------
__global__ __launch_bounds__(256) void convert_emb(const float* __restrict__ emb)
{
    const size_t idx = ((size_t)blockIdx.x * 256 + threadIdx.x) * 8;
    if (idx >= (size_t)30522 * DD) return;
    const float4 a = *(const float4*)(emb + idx);
    const float4 b = *(const float4*)(emb + idx + 4);
    __half2 h0 = __floats2half2_rn(a.x, a.y);
    __half2 h1 = __floats2half2_rn(a.z, a.w);
    __half2 h2 = __floats2half2_rn(b.x, b.y);
    __half2 h3 = __floats2half2_rn(b.z, b.w);
    uint4 o;
    o.x = *(uint32_t*)&h0; o.y = *(uint32_t*)&h1;
    o.z = *(uint32_t*)&h2; o.w = *(uint32_t*)&h3;
    *(uint4*)(g_emb16 + idx) = o;
}

// ---------------------------------------------------------------------------
// Stage 1a: partial pooling over fp16 table. grid (BB, PSL); 128 tokens/block.
// 192 threads = 96 column-groups (8 halves each) x 2 token-parity groups.
// fp16 pair-add (hadd2) before fp32 accumulate; smem reduce across parity.
// ---------------------------------------------------------------------------
__global__ __launch_bounds__(192) void pool_partial(
    const int* __restrict__ ids,
    const int* __restrict__ mask)
{
    const int b  = blockIdx.x;
    const int sl = blockIdx.y;
    const int t  = threadIdx.x;

    __shared__ __align__(16) int s_ids[128];
    __shared__ __align__(16) float s_red[96 * 8];
    __shared__ int s_cnt;
    if (t == 0) s_cnt = 0;
    __syncthreads();

    if (t < 128) {
        const int off = b * SS + sl * 128 + t;
        if (mask[off] != 0) {
            const int pos = atomicAdd(&s_cnt, 1);
            s_ids[pos] = ids[off];
        }
    }
    __syncthreads();
    const int cnt = s_cnt;

    const int tg  = (t >= 96) ? 1 : 0;
    const int tc  = t - tg * 96;
    const int col = tc * 8;

    float a[8];
#pragma unroll
    for (int j = 0; j < 8; j++) a[j] = 0.f;

    int s = tg;
    for (; s + 6 < cnt; s += 8) {
        const uint4 u0 = *(const uint4*)(g_emb16 + (size_t)s_ids[s + 0] * DD + col);
        const uint4 u1 = *(const uint4*)(g_emb16 + (size_t)s_ids[s + 2] * DD + col);
        const uint4 u2 = *(const uint4*)(g_emb16 + (size_t)s_ids[s + 4] * DD + col);
        const uint4 u3 = *(const uint4*)(g_emb16 + (size_t)s_ids[s + 6] * DD + col);
        const uint32_t* w0 = &u0.x;
        const uint32_t* w1 = &u1.x;
        const uint32_t* w2 = &u2.x;
        const uint32_t* w3 = &u3.x;
#pragma unroll
        for (int j = 0; j < 4; j++) {
            const __half2 p01 = __hadd2(*(const __half2*)&w0[j], *(const __half2*)&w1[j]);
            const __half2 p23 = __hadd2(*(const __half2*)&w2[j], *(const __half2*)&w3[j]);
            const float2 f01 = __half22float2(p01);
            const float2 f23 = __half22float2(p23);
            a[2 * j + 0] += f01.x + f23.x;
            a[2 * j + 1] += f01.y + f23.y;
        }
    }
    for (; s < cnt; s += 2) {
        const uint4 u = *(const uint4*)(g_emb16 + (size_t)s_ids[s] * DD + col);
        const uint32_t* w = &u.x;
#pragma unroll
        for (int j = 0; j < 4; j++) {
            const float2 f = __half22float2(*(const __half2*)&w[j]);
            a[2 * j + 0] += f.x;
            a[2 * j + 1] += f.y;
        }
    }

    if (tg) {
        *(float4*)(&s_red[col + 0]) = make_float4(a[0], a[1], a[2], a[3]);
        *(float4*)(&s_red[col + 4]) = make_float4(a[4], a[5], a[6], a[7]);
    }
    __syncthreads();
    if (!tg) {
        const float4 r0 = *(const float4*)(&s_red[col + 0]);
        const float4 r1 = *(const float4*)(&s_red[col + 4]);
        *(float4*)(&g_part[sl][b][col + 0]) =
            make_float4(a[0] + r0.x, a[1] + r0.y, a[2] + r0.z, a[3] + r0.w);
        *(float4*)(&g_part[sl][b][col + 4]) =
            make_float4(a[4] + r1.x, a[5] + r1.y, a[6] + r1.z, a[7] + r1.w);
    }
    if (t == 0) g_cntf[sl][b] = (float)cnt;
}

// ---------------------------------------------------------------------------
// Stage 1b: combine slices, emit bow as bf16 (hi, lo) split.
// ---------------------------------------------------------------------------
__global__ __launch_bounds__(192) void pool_combine_split(void)
{
    const int b = blockIdx.x;
    const int t = threadIdx.x;
    const float inv = 1.0f / (g_cntf[0][b] + g_cntf[1][b]);
    float v[4] = {0.f, 0.f, 0.f, 0.f};
#pragma unroll
    for (int sl = 0; sl < PSL; sl++) {
        const float4 p = *((const float4*)(&g_part[sl][b][0]) + t);
        v[0] += p.x; v[1] += p.y; v[2] += p.z; v[3] += p.w;
    }
#pragma unroll
    for (int c = 0; c < 4; c++) v[c] *= inv;

    unsigned short hi[4], lo[4];
#pragma unroll
    for (int c = 0; c < 4; c++) {
        __nv_bfloat16 hb = __float2bfloat16(v[c]);
        float r = v[c] - __bfloat162float(hb);
        __nv_bfloat16 lb = __float2bfloat16(r);
        hi[c] = __bfloat16_as_ushort(hb);
        lo[c] = __bfloat16_as_ushort(lb);
    }
    const size_t idx = (size_t)b * DD + t * 4;
    uint2 ph = make_uint2(((uint32_t)hi[1] << 16) | hi[0], ((uint32_t)hi[3] << 16) | hi[2]);
    uint2 pl = make_uint2(((uint32_t)lo[1] << 16) | lo[0], ((uint32_t)lo[3] << 16) | lo[2]);
    *(uint2*)(g_bow_hi + idx) = ph;
    *(uint2*)(g_bow_lo + idx) = pl;
}

// ---------------------------------------------------------------------------
// Convert W1 fp32 -> (hi, lo) bf16 pair.
// ---------------------------------------------------------------------------
__global__ __launch_bounds__(256) void convert_w1(const float* __restrict__ W1)
{
    const int i = (blockIdx.x * 256 + threadIdx.x) * 4;
    const float4 v4 = *(const float4*)(W1 + i);
    const float v[4] = {v4.x, v4.y, v4.z, v4.w};
    unsigned short hi[4], lo[4];
#pragma unroll
    for (int c = 0; c < 4; c++) {
        __nv_bfloat16 hb = __float2bfloat16(v[c]);
        float r = v[c] - __bfloat162float(hb);
        __nv_bfloat16 lb = __float2bfloat16(r);
        hi[c] = __bfloat16_as_ushort(hb);
        lo[c] = __bfloat16_as_ushort(lb);
    }
    uint2 ph = make_uint2(((uint32_t)hi[1] << 16) | hi[0], ((uint32_t)hi[3] << 16) | hi[2]);
    uint2 pl = make_uint2(((uint32_t)lo[1] << 16) | lo[0], ((uint32_t)lo[3] << 16) | lo[2]);
    *(uint2*)(g_w1_hi + i) = ph;
    *(uint2*)(g_w1_lo + i) = pl;
}

// ---------------------------------------------------------------------------
// Convert W2 fp32 [768][100] -> zero-padded bf16 hi/lo [768][128].
// ---------------------------------------------------------------------------
__global__ __launch_bounds__(256) void convert_w2(const float* __restrict__ W2)
{
    const int idx = blockIdx.x * 256 + threadIdx.x;
    const int k = idx >> 5;
    const int c = (idx & 31) * 4;
    unsigned short hi[4], lo[4];
#pragma unroll
    for (int j = 0; j < 4; j++) {
        const int col = c + j;
        const float v = (col < CC) ? W2[(size_t)k * CC + col] : 0.f;
        __nv_bfloat16 hb = __float2bfloat16(v);
        float r = v - __bfloat162float(hb);
        __nv_bfloat16 lb = __float2bfloat16(r);
        hi[j] = __bfloat16_as_ushort(hb);
        lo[j] = __bfloat16_as_ushort(lb);
    }
    const size_t o = (size_t)k * NP + c;
    *(uint2*)(g_w2p_hi + o) = make_uint2(((uint32_t)hi[1] << 16) | hi[0],
                                         ((uint32_t)hi[3] << 16) | hi[2]);
    *(uint2*)(g_w2p_lo + o) = make_uint2(((uint32_t)lo[1] << 16) | lo[0],
                                         ((uint32_t)lo[3] << 16) | lo[2]);
}

// ---------------------------------------------------------------------------
// Tensor-core + cp.async helpers
// ---------------------------------------------------------------------------
__device__ __forceinline__ uint32_t smem_u32(const void* p)
{
    return (uint32_t)__cvta_generic_to_shared(p);
}
__device__ __forceinline__ void cp16(uint32_t dst, const void* src)
{
    asm volatile("cp.async.cg.shared.global [%0], [%1], 16;" :: "r"(dst), "l"(src));
}
#define CP_COMMIT() asm volatile("cp.async.commit_group;" ::: "memory")
#define CP_WAIT0()  asm volatile("cp.async.wait_group 0;" ::: "memory")
__device__ __forceinline__ void ldsm4(uint32_t* r, uint32_t a)
{
    asm volatile("ldmatrix.sync.aligned.m8n8.x4.shared.b16 {%0,%1,%2,%3},[%4];"
                 : "=r"(r[0]), "=r"(r[1]), "=r"(r[2]), "=r"(r[3]) : "r"(a));
}
__device__ __forceinline__ void ldsm4t(uint32_t* r, uint32_t a)
{
    asm volatile("ldmatrix.sync.aligned.m8n8.x4.trans.shared.b16 {%0,%1,%2,%3},[%4];"
                 : "=r"(r[0]), "=r"(r[1]), "=r"(r[2]), "=r"(r[3]) : "r"(a));
}
__device__ __forceinline__ void mma_bf16(float* d, const uint32_t* a, const uint32_t* b)
{
    asm volatile(
        "mma.sync.aligned.m16n8k16.row.col.f32.bf16.bf16.f32 "
        "{%0,%1,%2,%3}, {%4,%5,%6,%7}, {%8,%9}, {%0,%1,%2,%3};"
        : "+f"(d[0]), "+f"(d[1]), "+f"(d[2]), "+f"(d[3])
        : "r"(a[0]), "r"(a[1]), "r"(a[2]), "r"(a[3]), "r"(b[0]), "r"(b[1]));
}
__device__ __forceinline__ uint32_t pack_bf16x2_hi(float a, float b,
                                                   unsigned short* la, unsigned short* lb)
{
    __nv_bfloat16 ha = __float2bfloat16(a);
    __nv_bfloat16 hb = __float2bfloat16(b);
    *la = __bfloat16_as_ushort(__float2bfloat16(a - __bfloat162float(ha)));
    *lb = __bfloat16_as_ushort(__float2bfloat16(b - __bfloat162float(hb)));
    return (uint32_t)__bfloat16_as_ushort(ha) | ((uint32_t)__bfloat16_as_ushort(hb) << 16);
}

// ---------------------------------------------------------------------------
// gemm1: h = relu(bow @ W1 + b1), bf16-split x3, BK=32, cp.async pipeline.
// BM=128, BN=96. grid (8, 16) = 128 CTAs. 8 warps 4(m) x 2(n).
// ---------------------------------------------------------------------------
#define AST32 40   // A smem row stride (halves) = 80 B
#define BST 104    // B smem row stride (halves) = 208 B
#define SA_HALVES (2 * 2 * 128 * AST32)   // 20480
#define SB_HALVES (2 * 2 * 32 * BST)      // 13312
#define G1_SMEM ((SA_HALVES + SB_HALVES) * 2)   // 67584 bytes

__global__ __launch_bounds__(256) void gemm1_mma96(
    const float* __restrict__ bias)
{
    extern __shared__ __align__(16) __nv_bfloat16 smem[];
    __nv_bfloat16* sA = smem;
    __nv_bfloat16* sB = smem + SA_HALVES;

    const int tid    = threadIdx.x;
    const int lane   = tid & 31;
    const int wid    = tid >> 5;
    const int warp_m = wid & 3;
    const int warp_n = wid >> 2;

    const int block_row = blockIdx.y * 128;
    const int block_col = blockIdx.x * 96;

    // A fill: 128r x 32k x 2p = 1024 uint4 -> 4/thread
    int a_idx[4];
    const __nv_bfloat16* Aptr[4];
#pragma unroll
    for (int e = 0; e < 4; e++) {
        const int u = tid + e * 256;
        const int p = u >> 9;
        const int r = (u & 511) >> 2;
        const int c = (u & 3) * 8;
        a_idx[e] = p * (128 * AST32) + r * AST32 + c;
        Aptr[e] = (p ? g_bow_lo : g_bow_hi) + (size_t)(block_row + r) * DD + c;
    }
    // B fill: 32k x 96c x 2p = 768 uint4 -> 3/thread
    int b_idx[3];
    const __nv_bfloat16* Bptr[3];
#pragma unroll
    for (int e = 0; e < 3; e++) {
        const int u = tid + e * 256;
        const int p = u / 384;
        const int rem = u - p * 384;
        const int r = rem / 12;
        const int c = (rem - r * 12) * 8;
        b_idx[e] = p * (32 * BST) + r * BST + c;
        Bptr[e] = (p ? g_w1_lo : g_w1_hi) + (size_t)r * DD + block_col + c;
    }

    float acc[2][6][4];
#pragma unroll
    for (int mt = 0; mt < 2; mt++)
#pragma unroll
        for (int nt = 0; nt < 6; nt++)
#pragma unroll
            for (int q = 0; q < 4; q++) acc[mt][nt][q] = 0.f;

    // preload k-tile 0 into stage 0 via cp.async
#pragma unroll
    for (int e = 0; e < 4; e++)
        cp16(smem_u32(&sA[a_idx[e]]), Aptr[e]);
#pragma unroll
    for (int e = 0; e < 3; e++)
        cp16(smem_u32(&sB[b_idx[e]]), Bptr[e]);
    CP_COMMIT();
    CP_WAIT0();
    __syncthreads();

    const int NT = DD / 32;   // 24
    for (int kt = 0; kt < NT; kt++) {
        const int cur = kt & 1;
        const int nxt = cur ^ 1;
        const bool has_next = (kt + 1 < NT);
        const int curA = cur * (2 * 128 * AST32);
        const int curB = cur * (2 * 32 * BST);

        if (has_next) {
            const int k0 = (kt + 1) * 32;
            const int nxtA = nxt * (2 * 128 * AST32);
            const int nxtB = nxt * (2 * 32 * BST);
#pragma unroll
            for (int e = 0; e < 4; e++)
                cp16(smem_u32(&sA[nxtA + a_idx[e]]), Aptr[e] + k0);
#pragma unroll
            for (int e = 0; e < 3; e++)
                cp16(smem_u32(&sB[nxtB + b_idx[e]]), Bptr[e] + (size_t)k0 * DD);
            CP_COMMIT();
        }

#pragma unroll
        for (int ks = 0; ks < 2; ks++) {
            uint32_t af[2][2][4];
#pragma unroll
            for (int p = 0; p < 2; p++)
#pragma unroll
                for (int mt = 0; mt < 2; mt++) {
                    const int off = curA + p * (128 * AST32)
                        + (warp_m * 32 + mt * 16 + (lane & 15)) * AST32
                        + ks * 16 + (lane >> 4) * 8;
                    ldsm4(af[p][mt], smem_u32(&sA[off]));
                }
            uint32_t bfr[2][6][2];
#pragma unroll
            for (int p = 0; p < 2; p++)
#pragma unroll
                for (int g = 0; g < 3; g++) {
                    const int off = curB + p * (32 * BST)
                        + (ks * 16 + (lane & 15)) * BST
                        + warp_n * 48 + g * 16 + (lane >> 4) * 8;
                    uint32_t r[4];
                    ldsm4t(r, smem_u32(&sB[off]));
                    bfr[p][2 * g + 0][0] = r[0]; bfr[p][2 * g + 0][1] = r[1];
                    bfr[p][2 * g + 1][0] = r[2]; bfr[p][2 * g + 1][1] = r[3];
                }
#pragma unroll
            for (int mt = 0; mt < 2; mt++)
#pragma unroll
                for (int nt = 0; nt < 6; nt++)
                    mma_bf16(acc[mt][nt], af[0][mt], bfr[0][nt]);
#pragma unroll
            for (int mt = 0; mt < 2; mt++)
#pragma unroll
                for (int nt = 0; nt < 6; nt++)
                    mma_bf16(acc[mt][nt], af[0][mt], bfr[1][nt]);
#pragma unroll
            for (int mt = 0; mt < 2; mt++)
#pragma unroll
                for (int nt = 0; nt < 6; nt++)
                    mma_bf16(acc[mt][nt], af[1][mt], bfr[0][nt]);
        }

        if (has_next) {
            CP_WAIT0();
            __syncthreads();
        }
    }

    // epilogue: bias + relu, emit h as bf16 hi/lo planes
#pragma unroll
    for (int mt = 0; mt < 2; mt++) {
        const int row0 = block_row + warp_m * 32 + mt * 16 + (lane >> 2);
#pragma unroll
        for (int nt = 0; nt < 6; nt++) {
            const int col = block_col + warp_n * 48 + nt * 8 + (lane & 3) * 2;
            const float b0 = bias[col], b1v = bias[col + 1];
            const float v0x = fmaxf(acc[mt][nt][0] + b0, 0.f);
            const float v0y = fmaxf(acc[mt][nt][1] + b1v, 0.f);
            const float v1x = fmaxf(acc[mt][nt][2] + b0, 0.f);
            const float v1y = fmaxf(acc[mt][nt][3] + b1v, 0.f);
            unsigned short l0, l1, l2, l3;
            const uint32_t h0 = pack_bf16x2_hi(v0x, v0y, &l0, &l1);
            const uint32_t h1 = pack_bf16x2_hi(v1x, v1y, &l2, &l3);
            *(uint32_t*)(g_h_hi + (size_t)row0 * DD + col) = h0;
            *(uint32_t*)(g_h_lo + (size_t)row0 * DD + col) =
                (uint32_t)l0 | ((uint32_t)l1 << 16);
            *(uint32_t*)(g_h_hi + (size_t)(row0 + 8) * DD + col) = h1;
            *(uint32_t*)(g_h_lo + (size_t)(row0 + 8) * DD + col) =
                (uint32_t)l2 | ((uint32_t)l3 << 16);
        }
    }
}

// ---------------------------------------------------------------------------
// gemm2: partial[ksl] = h[64 rows, kslice=192] @ W2pad[., 128], bf16-split x3.
// BM=64, BN=128, BK=16. grid (G2K, 32) = 128 CTAs.
// ---------------------------------------------------------------------------
#define AST 24
#define BST2 136

__global__ __launch_bounds__(256) void gemm2_mma(void)
{
    __shared__ __align__(16) __nv_bfloat16 sA[2][2][64 * AST];
    __shared__ __align__(16) __nv_bfloat16 sB[2][2][16 * BST2];

    const int tid    = threadIdx.x;
    const int lane   = tid & 31;
    const int wid    = tid >> 5;
    const int warp_m = wid & 1;
    const int warp_n = wid >> 1;

    const int ksl       = blockIdx.x;
    const int block_row = blockIdx.y * 64;
    const int kbase     = ksl * (DD / G2K);

    const int a_p = tid >> 7;
    const int a_r = (tid & 127) >> 1;
    const int a_c = (tid & 1) * 8;
    const __nv_bfloat16* Aptr = (a_p ? g_h_lo : g_h_hi)
                                + (size_t)(block_row + a_r) * DD + kbase + a_c;
    int b_p[2], b_r[2], b_c[2];
    const __nv_bfloat16* Bptr[2];
#pragma unroll
    for (int e = 0; e < 2; e++) {
        const int u = tid + e * 256;
        b_p[e] = u >> 8;
        b_r[e] = (u & 255) >> 4;
        b_c[e] = (u & 15) * 8;
        Bptr[e] = (b_p[e] ? g_w2p_lo : g_w2p_hi)
                  + (size_t)(kbase + b_r[e]) * NP + b_c[e];
    }

    float acc[2][4][4];
#pragma unroll
    for (int mt = 0; mt < 2; mt++)
#pragma unroll
        for (int nt = 0; nt < 4; nt++)
#pragma unroll
            for (int q = 0; q < 4; q++) acc[mt][nt][q] = 0.f;

    *(uint4*)&sA[0][a_p][a_r * AST + a_c] = *(const uint4*)(Aptr);
#pragma unroll
    for (int e = 0; e < 2; e++)
        *(uint4*)&sB[0][b_p[e]][b_r[e] * BST2 + b_c[e]] = *(const uint4*)(Bptr[e]);
    __syncthreads();

    const int NT = (DD / G2K) / 16;
    int aoff[2];
#pragma unroll
    for (int mt = 0; mt < 2; mt++)
        aoff[mt] = (warp_m * 32 + mt * 16 + (lane & 15)) * AST + (lane >> 4) * 8;
    int boff[2];
#pragma unroll
    for (int g = 0; g < 2; g++)
        boff[g] = (lane & 15) * BST2 + warp_n * 32 + g * 16 + (lane >> 4) * 8;

    for (int kt = 0; kt < NT; kt++) {
        const int cur = kt & 1;
        const int nxt = cur ^ 1;
        const bool has_next = (kt + 1 < NT);

        uint4 pa, pb[2];
        if (has_next) {
            const int k0 = (kt + 1) * 16;
            pa = *(const uint4*)(Aptr + k0);
#pragma unroll
            for (int e = 0; e < 2; e++)
                pb[e] = *(const uint4*)(Bptr[e] + (size_t)k0 * NP);
        }

        uint32_t af[2][2][4];
#pragma unroll
        for (int p = 0; p < 2; p++)
#pragma unroll
            for (int mt = 0; mt < 2; mt++)
                ldsm4(af[p][mt], smem_u32(&sA[cur][p][aoff[mt]]));

        uint32_t bfr[2][4][2];
#pragma unroll
        for (int p = 0; p < 2; p++)
#pragma unroll
            for (int g = 0; g < 2; g++) {
                uint32_t r[4];
                ldsm4t(r, smem_u32(&sB[cur][p][boff[g]]));
                bfr[p][2 * g + 0][0] = r[0]; bfr[p][2 * g + 0][1] = r[1];
                bfr[p][2 * g + 1][0] = r[2]; bfr[p][2 * g + 1][1] = r[3];
            }

#pragma unroll
        for (int mt = 0; mt < 2; mt++)
#pragma unroll
            for (int nt = 0; nt < 4; nt++)
                mma_bf16(acc[mt][nt], af[0][mt], bfr[0][nt]);
#pragma unroll
        for (int mt = 0; mt < 2; mt++)
#pragma unroll
            for (int nt = 0; nt < 4; nt++)
                mma_bf16(acc[mt][nt], af[0][mt], bfr[1][nt]);
#pragma unroll
        for (int mt = 0; mt < 2; mt++)
#pragma unroll
            for (int nt = 0; nt < 4; nt++)
                mma_bf16(acc[mt][nt], af[1][mt], bfr[0][nt]);

        if (has_next) {
            *(uint4*)&sA[nxt][a_p][a_r * AST + a_c] = pa;
#pragma unroll
            for (int e = 0; e < 2; e++)
                *(uint4*)&sB[nxt][b_p[e]][b_r[e] * BST2 + b_c[e]] = pb[e];
            __syncthreads();
        }
    }

#pragma unroll
    for (int mt = 0; mt < 2; mt++) {
        const int row0 = block_row + warp_m * 32 + mt * 16 + (lane >> 2);
#pragma unroll
        for (int nt = 0; nt < 4; nt++) {
            const int col = warp_n * 32 + nt * 8 + (lane & 3) * 2;
            *(float2*)(&g_p2[ksl][row0][col]) =
                make_float2(acc[mt][nt][0], acc[mt][nt][1]);
            *(float2*)(&g_p2[ksl][row0 + 8][col]) =
                make_float2(acc[mt][nt][2], acc[mt][nt][3]);
        }
    }
}

// ---------------------------------------------------------------------------
// Reduce gemm2 partials + bias, write both output copies.
// ---------------------------------------------------------------------------
__global__ __launch_bounds__(256) void reduce_kernel(
    const float* __restrict__ bias,
    float* __restrict__ out,
    float* __restrict__ out2)
{
    const int idx = blockIdx.x * 256 + threadIdx.x;
    if (idx >= BB * CC) return;
    const int b = idx / CC;
    const int c = idx - b * CC;
    float v = bias[c];
#pragma unroll
    for (int s = 0; s < G2K; s++) v += g_p2[s][b][c];
    out[idx] = v;
    if (out2) out2[idx] = v;
}

// ---------------------------------------------------------------------------
extern "C" void kernel_launch(void* const* d_in, const int* in_sizes, int n_in,
                              void* d_out, int out_size)
{
    const int*   input_ids = (const int*)d_in[0];
    const int*   attn_mask = (const int*)d_in[1];
    const float* emb       = (const float*)d_in[2];
    const float* W1        = (const float*)d_in[3];
    const float* b1        = (const float*)d_in[4];
    const float* W2        = (const float*)d_in[5];
    const float* b2        = (const float*)d_in[6];
    float*       out       = (float*)d_out;

    cudaFuncSetAttribute(gemm1_mma96, cudaFuncAttributeMaxDynamicSharedMemorySize, G1_SMEM);

    // Conversions
    {
        const size_t n_emb = (size_t)30522 * DD;
        convert_emb<<<(unsigned)((n_emb / 8 + 255) / 256), 256>>>(emb);
        convert_w1<<<(DD * DD) / (256 * 4), 256>>>(W1);
        convert_w2<<<(DD * 32) / 256, 256>>>(W2);
    }

    // Stage 1: pooling (fp16 gather, hadd2 pair-tree)
    {
        dim3 grid(BB, PSL);
        pool_partial<<<grid, 192>>>(input_ids, attn_mask);
        pool_combine_split<<<BB, 192>>>();
    }

    // Stage 2: h = relu(bow @ W1 + b1) -> bf16 hi/lo (BK=32, cp.async)
    {
        dim3 grid(DD / 96, BB / 128);    // (8, 16) = 128 CTAs
        gemm1_mma96<<<grid, 256, G1_SMEM>>>(b1);
    }

    // Stage 3: scores = h @ W2 + b2 (tensor-core split-K + reduce)
    {
        dim3 grid(G2K, BB / 64);         // (4, 32) = 128 CTAs
        gemm2_mma<<<grid, 256>>>();
        float* out2 = (out_size >= 2 * BB * CC) ? (out + (size_t)BB * CC) : nullptr;
        reduce_kernel<<<(BB * CC + 255) / 256, 256>>>(b2, out, out2);
    }
}

// round 16
// speedup vs baseline: 1.0817x; 1.0817x over previous
#include <cuda_runtime.h>
#include <cuda_bf16.h>
#include <cuda_fp16.h>
#include <cstdint>

#define BB 2048
#define SS 256
#define DD 768
#define CC 100
#define NP 128         // padded N for gemm2
#define G2K 4          // gemm2 K slices (192 each)

// Scratch (no cudaMalloc allowed)
__device__ __half g_emb16[(size_t)30522 * DD];
__device__ float g_p2[G2K][BB][NP];
__device__ __nv_bfloat16 g_bow_hi[(size_t)BB * DD];
__device__ __nv_bfloat16 g_bow_lo[(size_t)BB * DD];
__device__ __nv_bfloat16 g_w1_hi[(size_t)DD * DD];    // W1 row-major [K][N]
__device__ __nv_bfloat16 g_w1_lo[(size_t)DD * DD];
__device__ __nv_bfloat16 g_w2p_hi[(size_t)DD * NP];   // W2 padded [K][128]
__device__ __nv_bfloat16 g_w2p_lo[(size_t)DD * NP];
__device__ __nv_bfloat16 g_h_hi[(size_t)BB * DD];
__device__ __nv_bfloat16 g_h_lo[(size_t)BB * DD];

// ---------------------------------------------------------------------------
// Convert embedding table fp32 -> fp16.
// ---------------------------------------------------------------------------
__global__ __launch_bounds__(256) void convert_emb(const float* __restrict__ emb)
{
    const size_t idx = ((size_t)blockIdx.x * 256 + threadIdx.x) * 8;
    if (idx >= (size_t)30522 * DD) return;
    const float4 a = *(const float4*)(emb + idx);
    const float4 b = *(const float4*)(emb + idx + 4);
    __half2 h0 = __floats2half2_rn(a.x, a.y);
    __half2 h1 = __floats2half2_rn(a.z, a.w);
    __half2 h2 = __floats2half2_rn(b.x, b.y);
    __half2 h3 = __floats2half2_rn(b.z, b.w);
    uint4 o;
    o.x = *(uint32_t*)&h0; o.y = *(uint32_t*)&h1;
    o.z = *(uint32_t*)&h2; o.w = *(uint32_t*)&h3;
    *(uint4*)(g_emb16 + idx) = o;
}

// ---------------------------------------------------------------------------
// Fused pooling: one block per sample, 256 tokens, emits bow bf16 hi/lo.
// 192 threads = 96 column-groups (8 halves each) x 2 token-parity groups.
// fp16 pair-add (hadd2) before fp32 accumulate; smem reduce across parity.
// ---------------------------------------------------------------------------
__global__ __launch_bounds__(192) void pool_fused(
    const int* __restrict__ ids,
    const int* __restrict__ mask)
{
    const int b = blockIdx.x;
    const int t = threadIdx.x;

    __shared__ __align__(16) int s_ids[SS];
    __shared__ __align__(16) float s_red[96 * 8];
    __shared__ int s_cnt;
    if (t == 0) s_cnt = 0;
    __syncthreads();

    for (int s = t; s < SS; s += 192) {
        const int off = b * SS + s;
        if (mask[off] != 0) {
            const int pos = atomicAdd(&s_cnt, 1);
            s_ids[pos] = ids[off];
        }
    }
    __syncthreads();
    const int cnt = s_cnt;

    const int tg  = (t >= 96) ? 1 : 0;
    const int tc  = t - tg * 96;
    const int col = tc * 8;

    float a[8];
#pragma unroll
    for (int j = 0; j < 8; j++) a[j] = 0.f;

    int s = tg;
    for (; s + 6 < cnt; s += 8) {
        const uint4 u0 = *(const uint4*)(g_emb16 + (size_t)s_ids[s + 0] * DD + col);
        const uint4 u1 = *(const uint4*)(g_emb16 + (size_t)s_ids[s + 2] * DD + col);
        const uint4 u2 = *(const uint4*)(g_emb16 + (size_t)s_ids[s + 4] * DD + col);
        const uint4 u3 = *(const uint4*)(g_emb16 + (size_t)s_ids[s + 6] * DD + col);
        const uint32_t* w0 = &u0.x;
        const uint32_t* w1 = &u1.x;
        const uint32_t* w2 = &u2.x;
        const uint32_t* w3 = &u3.x;
#pragma unroll
        for (int j = 0; j < 4; j++) {
            const __half2 p01 = __hadd2(*(const __half2*)&w0[j], *(const __half2*)&w1[j]);
            const __half2 p23 = __hadd2(*(const __half2*)&w2[j], *(const __half2*)&w3[j]);
            const float2 f01 = __half22float2(p01);
            const float2 f23 = __half22float2(p23);
            a[2 * j + 0] += f01.x + f23.x;
            a[2 * j + 1] += f01.y + f23.y;
        }
    }
    for (; s < cnt; s += 2) {
        const uint4 u = *(const uint4*)(g_emb16 + (size_t)s_ids[s] * DD + col);
        const uint32_t* w = &u.x;
#pragma unroll
        for (int j = 0; j < 4; j++) {
            const float2 f = __half22float2(*(const __half2*)&w[j]);
            a[2 * j + 0] += f.x;
            a[2 * j + 1] += f.y;
        }
    }

    if (tg) {
        *(float4*)(&s_red[col + 0]) = make_float4(a[0], a[1], a[2], a[3]);
        *(float4*)(&s_red[col + 4]) = make_float4(a[4], a[5], a[6], a[7]);
    }
    __syncthreads();
    if (!tg) {
        const float inv = 1.0f / (float)cnt;   // cnt >= 1 guaranteed
        const float4 r0 = *(const float4*)(&s_red[col + 0]);
        const float4 r1 = *(const float4*)(&s_red[col + 4]);
        float v[8];
        v[0] = (a[0] + r0.x) * inv; v[1] = (a[1] + r0.y) * inv;
        v[2] = (a[2] + r0.z) * inv; v[3] = (a[3] + r0.w) * inv;
        v[4] = (a[4] + r1.x) * inv; v[5] = (a[5] + r1.y) * inv;
        v[6] = (a[6] + r1.z) * inv; v[7] = (a[7] + r1.w) * inv;

        unsigned short hi[8], lo[8];
#pragma unroll
        for (int c = 0; c < 8; c++) {
            __nv_bfloat16 hb = __float2bfloat16(v[c]);
            float r = v[c] - __bfloat162float(hb);
            __nv_bfloat16 lb = __float2bfloat16(r);
            hi[c] = __bfloat16_as_ushort(hb);
            lo[c] = __bfloat16_as_ushort(lb);
        }
        const size_t idx = (size_t)b * DD + col;
        uint4 ph, pl;
        ph.x = (uint32_t)hi[0] | ((uint32_t)hi[1] << 16);
        ph.y = (uint32_t)hi[2] | ((uint32_t)hi[3] << 16);
        ph.z = (uint32_t)hi[4] | ((uint32_t)hi[5] << 16);
        ph.w = (uint32_t)hi[6] | ((uint32_t)hi[7] << 16);
        pl.x = (uint32_t)lo[0] | ((uint32_t)lo[1] << 16);
        pl.y = (uint32_t)lo[2] | ((uint32_t)lo[3] << 16);
        pl.z = (uint32_t)lo[4] | ((uint32_t)lo[5] << 16);
        pl.w = (uint32_t)lo[6] | ((uint32_t)lo[7] << 16);
        *(uint4*)(g_bow_hi + idx) = ph;
        *(uint4*)(g_bow_lo + idx) = pl;
    }
}

// ---------------------------------------------------------------------------
// Convert W1 fp32 -> (hi, lo) bf16 pair.
// ---------------------------------------------------------------------------
__global__ __launch_bounds__(256) void convert_w1(const float* __restrict__ W1)
{
    const int i = (blockIdx.x * 256 + threadIdx.x) * 4;
    const float4 v4 = *(const float4*)(W1 + i);
    const float v[4] = {v4.x, v4.y, v4.z, v4.w};
    unsigned short hi[4], lo[4];
#pragma unroll
    for (int c = 0; c < 4; c++) {
        __nv_bfloat16 hb = __float2bfloat16(v[c]);
        float r = v[c] - __bfloat162float(hb);
        __nv_bfloat16 lb = __float2bfloat16(r);
        hi[c] = __bfloat16_as_ushort(hb);
        lo[c] = __bfloat16_as_ushort(lb);
    }
    uint2 ph = make_uint2(((uint32_t)hi[1] << 16) | hi[0], ((uint32_t)hi[3] << 16) | hi[2]);
    uint2 pl = make_uint2(((uint32_t)lo[1] << 16) | lo[0], ((uint32_t)lo[3] << 16) | lo[2]);
    *(uint2*)(g_w1_hi + i) = ph;
    *(uint2*)(g_w1_lo + i) = pl;
}

// ---------------------------------------------------------------------------
// Convert W2 fp32 [768][100] -> zero-padded bf16 hi/lo [768][128].
// ---------------------------------------------------------------------------
__global__ __launch_bounds__(256) void convert_w2(const float* __restrict__ W2)
{
    const int idx = blockIdx.x * 256 + threadIdx.x;
    const int k = idx >> 5;
    const int c = (idx & 31) * 4;
    unsigned short hi[4], lo[4];
#pragma unroll
    for (int j = 0; j < 4; j++) {
        const int col = c + j;
        const float v = (col < CC) ? W2[(size_t)k * CC + col] : 0.f;
        __nv_bfloat16 hb = __float2bfloat16(v);
        float r = v - __bfloat162float(hb);
        __nv_bfloat16 lb = __float2bfloat16(r);
        hi[j] = __bfloat16_as_ushort(hb);
        lo[j] = __bfloat16_as_ushort(lb);
    }
    const size_t o = (size_t)k * NP + c;
    *(uint2*)(g_w2p_hi + o) = make_uint2(((uint32_t)hi[1] << 16) | hi[0],
                                         ((uint32_t)hi[3] << 16) | hi[2]);
    *(uint2*)(g_w2p_lo + o) = make_uint2(((uint32_t)lo[1] << 16) | lo[0],
                                         ((uint32_t)lo[3] << 16) | lo[2]);
}

// ---------------------------------------------------------------------------
// Tensor-core helpers
// ---------------------------------------------------------------------------
__device__ __forceinline__ uint32_t smem_u32(const void* p)
{
    return (uint32_t)__cvta_generic_to_shared(p);
}
__device__ __forceinline__ void ldsm4(uint32_t* r, uint32_t a)
{
    asm volatile("ldmatrix.sync.aligned.m8n8.x4.shared.b16 {%0,%1,%2,%3},[%4];"
                 : "=r"(r[0]), "=r"(r[1]), "=r"(r[2]), "=r"(r[3]) : "r"(a));
}
__device__ __forceinline__ void ldsm4t(uint32_t* r, uint32_t a)
{
    asm volatile("ldmatrix.sync.aligned.m8n8.x4.trans.shared.b16 {%0,%1,%2,%3},[%4];"
                 : "=r"(r[0]), "=r"(r[1]), "=r"(r[2]), "=r"(r[3]) : "r"(a));
}
__device__ __forceinline__ void mma_bf16(float* d, const uint32_t* a, const uint32_t* b)
{
    asm volatile(
        "mma.sync.aligned.m16n8k16.row.col.f32.bf16.bf16.f32 "
        "{%0,%1,%2,%3}, {%4,%5,%6,%7}, {%8,%9}, {%0,%1,%2,%3};"
        : "+f"(d[0]), "+f"(d[1]), "+f"(d[2]), "+f"(d[3])
        : "r"(a[0]), "r"(a[1]), "r"(a[2]), "r"(a[3]), "r"(b[0]), "r"(b[1]));
}
__device__ __forceinline__ uint32_t pack_bf16x2_hi(float a, float b,
                                                   unsigned short* la, unsigned short* lb)
{
    __nv_bfloat16 ha = __float2bfloat16(a);
    __nv_bfloat16 hb = __float2bfloat16(b);
    *la = __bfloat16_as_ushort(__float2bfloat16(a - __bfloat162float(ha)));
    *lb = __bfloat16_as_ushort(__float2bfloat16(b - __bfloat162float(hb)));
    return (uint32_t)__bfloat16_as_ushort(ha) | ((uint32_t)__bfloat16_as_ushort(hb) << 16);
}

// ---------------------------------------------------------------------------
// gemm1: h = relu(bow @ W1 + b1), bf16-split x3, BK=32, register prefetch
// (cp.async reverted: it cost ~6us). BM=128, BN=96. grid (8, 16) = 128 CTAs.
// 8 warps 4(m) x 2(n); warp tile 32x48. Dynamic smem 66 KB.
// ---------------------------------------------------------------------------
#define AST32 40   // A smem row stride (halves) = 80 B
#define BST 104    // B smem row stride (halves) = 208 B
#define SA_HALVES (2 * 2 * 128 * AST32)   // 20480
#define SB_HALVES (2 * 2 * 32 * BST)      // 13312
#define G1_SMEM ((SA_HALVES + SB_HALVES) * 2)   // 67584 bytes

__global__ __launch_bounds__(256) void gemm1_mma96(
    const float* __restrict__ bias)
{
    extern __shared__ __align__(16) __nv_bfloat16 smem[];
    __nv_bfloat16* sA = smem;
    __nv_bfloat16* sB = smem + SA_HALVES;

    const int tid    = threadIdx.x;
    const int lane   = tid & 31;
    const int wid    = tid >> 5;
    const int warp_m = wid & 3;
    const int warp_n = wid >> 2;

    const int block_row = blockIdx.y * 128;
    const int block_col = blockIdx.x * 96;

    // A fill: 128r x 32k x 2p = 1024 uint4 -> 4/thread
    int a_idx[4];
    const __nv_bfloat16* Aptr[4];
#pragma unroll
    for (int e = 0; e < 4; e++) {
        const int u = tid + e * 256;
        const int p = u >> 9;
        const int r = (u & 511) >> 2;
        const int c = (u & 3) * 8;
        a_idx[e] = p * (128 * AST32) + r * AST32 + c;
        Aptr[e] = (p ? g_bow_lo : g_bow_hi) + (size_t)(block_row + r) * DD + c;
    }
    // B fill: 32k x 96c x 2p = 768 uint4 -> 3/thread
    int b_idx[3];
    const __nv_bfloat16* Bptr[3];
#pragma unroll
    for (int e = 0; e < 3; e++) {
        const int u = tid + e * 256;
        const int p = u / 384;
        const int rem = u - p * 384;
        const int r = rem / 12;
        const int c = (rem - r * 12) * 8;
        b_idx[e] = p * (32 * BST) + r * BST + c;
        Bptr[e] = (p ? g_w1_lo : g_w1_hi) + (size_t)r * DD + block_col + c;
    }

    float acc[2][6][4];
#pragma unroll
    for (int mt = 0; mt < 2; mt++)
#pragma unroll
        for (int nt = 0; nt < 6; nt++)
#pragma unroll
            for (int q = 0; q < 4; q++) acc[mt][nt][q] = 0.f;

    // preload k-tile 0 into stage 0
#pragma unroll
    for (int e = 0; e < 4; e++)
        *(uint4*)&sA[a_idx[e]] = *(const uint4*)(Aptr[e]);
#pragma unroll
    for (int e = 0; e < 3; e++)
        *(uint4*)&sB[b_idx[e]] = *(const uint4*)(Bptr[e]);
    __syncthreads();

    const int NT = DD / 32;   // 24
    for (int kt = 0; kt < NT; kt++) {
        const int cur = kt & 1;
        const int nxt = cur ^ 1;
        const bool has_next = (kt + 1 < NT);
        const int curA = cur * (2 * 128 * AST32);
        const int curB = cur * (2 * 32 * BST);

        uint4 pa[4], pb[3];
        if (has_next) {
            const int k0 = (kt + 1) * 32;
#pragma unroll
            for (int e = 0; e < 4; e++)
                pa[e] = *(const uint4*)(Aptr[e] + k0);
#pragma unroll
            for (int e = 0; e < 3; e++)
                pb[e] = *(const uint4*)(Bptr[e] + (size_t)k0 * DD);
        }

#pragma unroll
        for (int ks = 0; ks < 2; ks++) {
            uint32_t af[2][2][4];
#pragma unroll
            for (int p = 0; p < 2; p++)
#pragma unroll
                for (int mt = 0; mt < 2; mt++) {
                    const int off = curA + p * (128 * AST32)
                        + (warp_m * 32 + mt * 16 + (lane & 15)) * AST32
                        + ks * 16 + (lane >> 4) * 8;
                    ldsm4(af[p][mt], smem_u32(&sA[off]));
                }
            uint32_t bfr[2][6][2];
#pragma unroll
            for (int p = 0; p < 2; p++)
#pragma unroll
                for (int g = 0; g < 3; g++) {
                    const int off = curB + p * (32 * BST)
                        + (ks * 16 + (lane & 15)) * BST
                        + warp_n * 48 + g * 16 + (lane >> 4) * 8;
                    uint32_t r[4];
                    ldsm4t(r, smem_u32(&sB[off]));
                    bfr[p][2 * g + 0][0] = r[0]; bfr[p][2 * g + 0][1] = r[1];
                    bfr[p][2 * g + 1][0] = r[2]; bfr[p][2 * g + 1][1] = r[3];
                }
#pragma unroll
            for (int mt = 0; mt < 2; mt++)
#pragma unroll
                for (int nt = 0; nt < 6; nt++)
                    mma_bf16(acc[mt][nt], af[0][mt], bfr[0][nt]);
#pragma unroll
            for (int mt = 0; mt < 2; mt++)
#pragma unroll
                for (int nt = 0; nt < 6; nt++)
                    mma_bf16(acc[mt][nt], af[0][mt], bfr[1][nt]);
#pragma unroll
            for (int mt = 0; mt < 2; mt++)
#pragma unroll
                for (int nt = 0; nt < 6; nt++)
                    mma_bf16(acc[mt][nt], af[1][mt], bfr[0][nt]);
        }

        if (has_next) {
            const int nxtA = nxt * (2 * 128 * AST32);
            const int nxtB = nxt * (2 * 32 * BST);
#pragma unroll
            for (int e = 0; e < 4; e++)
                *(uint4*)&sA[nxtA + a_idx[e]] = pa[e];
#pragma unroll
            for (int e = 0; e < 3; e++)
                *(uint4*)&sB[nxtB + b_idx[e]] = pb[e];
            __syncthreads();
        }
    }

    // epilogue: bias + relu, emit h as bf16 hi/lo planes
#pragma unroll
    for (int mt = 0; mt < 2; mt++) {
        const int row0 = block_row + warp_m * 32 + mt * 16 + (lane >> 2);
#pragma unroll
        for (int nt = 0; nt < 6; nt++) {
            const int col = block_col + warp_n * 48 + nt * 8 + (lane & 3) * 2;
            const float b0 = bias[col], b1v = bias[col + 1];
            const float v0x = fmaxf(acc[mt][nt][0] + b0, 0.f);
            const float v0y = fmaxf(acc[mt][nt][1] + b1v, 0.f);
            const float v1x = fmaxf(acc[mt][nt][2] + b0, 0.f);
            const float v1y = fmaxf(acc[mt][nt][3] + b1v, 0.f);
            unsigned short l0, l1, l2, l3;
            const uint32_t h0 = pack_bf16x2_hi(v0x, v0y, &l0, &l1);
            const uint32_t h1 = pack_bf16x2_hi(v1x, v1y, &l2, &l3);
            *(uint32_t*)(g_h_hi + (size_t)row0 * DD + col) = h0;
            *(uint32_t*)(g_h_lo + (size_t)row0 * DD + col) =
                (uint32_t)l0 | ((uint32_t)l1 << 16);
            *(uint32_t*)(g_h_hi + (size_t)(row0 + 8) * DD + col) = h1;
            *(uint32_t*)(g_h_lo + (size_t)(row0 + 8) * DD + col) =
                (uint32_t)l2 | ((uint32_t)l3 << 16);
        }
    }
}

// ---------------------------------------------------------------------------
// gemm2: partial[ksl] = h[64 rows, kslice=192] @ W2pad[., 128], bf16-split x3.
// BM=64, BN=128, BK=16. grid (G2K, 32) = 128 CTAs.
// ---------------------------------------------------------------------------
#define AST 24
#define BST2 136

__global__ __launch_bounds__(256) void gemm2_mma(void)
{
    __shared__ __align__(16) __nv_bfloat16 sA[2][2][64 * AST];
    __shared__ __align__(16) __nv_bfloat16 sB[2][2][16 * BST2];

    const int tid    = threadIdx.x;
    const int lane   = tid & 31;
    const int wid    = tid >> 5;
    const int warp_m = wid & 1;
    const int warp_n = wid >> 1;

    const int ksl       = blockIdx.x;
    const int block_row = blockIdx.y * 64;
    const int kbase     = ksl * (DD / G2K);

    const int a_p = tid >> 7;
    const int a_r = (tid & 127) >> 1;
    const int a_c = (tid & 1) * 8;
    const __nv_bfloat16* Aptr = (a_p ? g_h_lo : g_h_hi)
                                + (size_t)(block_row + a_r) * DD + kbase + a_c;
    int b_p[2], b_r[2], b_c[2];
    const __nv_bfloat16* Bptr[2];
#pragma unroll
    for (int e = 0; e < 2; e++) {
        const int u = tid + e * 256;
        b_p[e] = u >> 8;
        b_r[e] = (u & 255) >> 4;
        b_c[e] = (u & 15) * 8;
        Bptr[e] = (b_p[e] ? g_w2p_lo : g_w2p_hi)
                  + (size_t)(kbase + b_r[e]) * NP + b_c[e];
    }

    float acc[2][4][4];
#pragma unroll
    for (int mt = 0; mt < 2; mt++)
#pragma unroll
        for (int nt = 0; nt < 4; nt++)
#pragma unroll
            for (int q = 0; q < 4; q++) acc[mt][nt][q] = 0.f;

    *(uint4*)&sA[0][a_p][a_r * AST + a_c] = *(const uint4*)(Aptr);
#pragma unroll
    for (int e = 0; e < 2; e++)
        *(uint4*)&sB[0][b_p[e]][b_r[e] * BST2 + b_c[e]] = *(const uint4*)(Bptr[e]);
    __syncthreads();

    const int NT = (DD / G2K) / 16;
    int aoff[2];
#pragma unroll
    for (int mt = 0; mt < 2; mt++)
        aoff[mt] = (warp_m * 32 + mt * 16 + (lane & 15)) * AST + (lane >> 4) * 8;
    int boff[2];
#pragma unroll
    for (int g = 0; g < 2; g++)
        boff[g] = (lane & 15) * BST2 + warp_n * 32 + g * 16 + (lane >> 4) * 8;

    for (int kt = 0; kt < NT; kt++) {
        const int cur = kt & 1;
        const int nxt = cur ^ 1;
        const bool has_next = (kt + 1 < NT);

        uint4 pa, pb[2];
        if (has_next) {
            const int k0 = (kt + 1) * 16;
            pa = *(const uint4*)(Aptr + k0);
#pragma unroll
            for (int e = 0; e < 2; e++)
                pb[e] = *(const uint4*)(Bptr[e] + (size_t)k0 * NP);
        }

        uint32_t af[2][2][4];
#pragma unroll
        for (int p = 0; p < 2; p++)
#pragma unroll
            for (int mt = 0; mt < 2; mt++)
                ldsm4(af[p][mt], smem_u32(&sA[cur][p][aoff[mt]]));

        uint32_t bfr[2][4][2];
#pragma unroll
        for (int p = 0; p < 2; p++)
#pragma unroll
            for (int g = 0; g < 2; g++) {
                uint32_t r[4];
                ldsm4t(r, smem_u32(&sB[cur][p][boff[g]]));
                bfr[p][2 * g + 0][0] = r[0]; bfr[p][2 * g + 0][1] = r[1];
                bfr[p][2 * g + 1][0] = r[2]; bfr[p][2 * g + 1][1] = r[3];
            }

#pragma unroll
        for (int mt = 0; mt < 2; mt++)
#pragma unroll
            for (int nt = 0; nt < 4; nt++)
                mma_bf16(acc[mt][nt], af[0][mt], bfr[0][nt]);
#pragma unroll
        for (int mt = 0; mt < 2; mt++)
#pragma unroll
            for (int nt = 0; nt < 4; nt++)
                mma_bf16(acc[mt][nt], af[0][mt], bfr[1][nt]);
#pragma unroll
        for (int mt = 0; mt < 2; mt++)
#pragma unroll
            for (int nt = 0; nt < 4; nt++)
                mma_bf16(acc[mt][nt], af[1][mt], bfr[0][nt]);

        if (has_next) {
            *(uint4*)&sA[nxt][a_p][a_r * AST + a_c] = pa;
#pragma unroll
            for (int e = 0; e < 2; e++)
                *(uint4*)&sB[nxt][b_p[e]][b_r[e] * BST2 + b_c[e]] = pb[e];
            __syncthreads();
        }
    }

#pragma unroll
    for (int mt = 0; mt < 2; mt++) {
        const int row0 = block_row + warp_m * 32 + mt * 16 + (lane >> 2);
#pragma unroll
        for (int nt = 0; nt < 4; nt++) {
            const int col = warp_n * 32 + nt * 8 + (lane & 3) * 2;
            *(float2*)(&g_p2[ksl][row0][col]) =
                make_float2(acc[mt][nt][0], acc[mt][nt][1]);
            *(float2*)(&g_p2[ksl][row0 + 8][col]) =
                make_float2(acc[mt][nt][2], acc[mt][nt][3]);
        }
    }
}

// ---------------------------------------------------------------------------
// Reduce gemm2 partials + bias, write both output copies.
// ---------------------------------------------------------------------------
__global__ __launch_bounds__(256) void reduce_kernel(
    const float* __restrict__ bias,
    float* __restrict__ out,
    float* __restrict__ out2)
{
    const int idx = blockIdx.x * 256 + threadIdx.x;
    if (idx >= BB * CC) return;
    const int b = idx / CC;
    const int c = idx - b * CC;
    float v = bias[c];
#pragma unroll
    for (int s = 0; s < G2K; s++) v += g_p2[s][b][c];
    out[idx] = v;
    if (out2) out2[idx] = v;
}

// ---------------------------------------------------------------------------
extern "C" void kernel_launch(void* const* d_in, const int* in_sizes, int n_in,
                              void* d_out, int out_size)
{
    const int*   input_ids = (const int*)d_in[0];
    const int*   attn_mask = (const int*)d_in[1];
    const float* emb       = (const float*)d_in[2];
    const float* W1        = (const float*)d_in[3];
    const float* b1        = (const float*)d_in[4];
    const float* W2        = (const float*)d_in[5];
    const float* b2        = (const float*)d_in[6];
    float*       out       = (float*)d_out;

    cudaFuncSetAttribute(gemm1_mma96, cudaFuncAttributeMaxDynamicSharedMemorySize, G1_SMEM);

    // Conversions
    {
        const size_t n_emb = (size_t)30522 * DD;
        convert_emb<<<(unsigned)((n_emb / 8 + 255) / 256), 256>>>(emb);
        convert_w1<<<(DD * DD) / (256 * 4), 256>>>(W1);
        convert_w2<<<(DD * 32) / 256, 256>>>(W2);
    }

    // Stage 1: fused pooling (fp16 gather -> bow bf16 hi/lo directly)
    pool_fused<<<BB, 192>>>(input_ids, attn_mask);

    // Stage 2: h = relu(bow @ W1 + b1) -> bf16 hi/lo (BK=32, reg prefetch)
    {
        dim3 grid(DD / 96, BB / 128);    // (8, 16) = 128 CTAs
        gemm1_mma96<<<grid, 256, G1_SMEM>>>(b1);
    }

    // Stage 3: scores = h @ W2 + b2 (tensor-core split-K + reduce)
    {
        dim3 grid(G2K, BB / 64);         // (4, 32) = 128 CTAs
        gemm2_mma<<<grid, 256>>>();
        float* out2 = (out_size >= 2 * BB * CC) ? (out + (size_t)BB * CC) : nullptr;
        reduce_kernel<<<(BB * CC + 255) / 256, 256>>>(b2, out, out2);
    }
}